// round 12
// baseline (speedup 1.0000x reference)
#include <cuda_runtime.h>

// ---------------------------------------------------------------------------
// Compile-time filter construction (double precision, folded to fp32 imms)
// ---------------------------------------------------------------------------
__host__ __device__ constexpr double d_abs(double x){ return x < 0 ? -x : x; }
__host__ __device__ constexpr double cexp_pos(double x){ double t=1.0,s=1.0; for(int n=1;n<60;n++){ t*=x/n; s+=t; } return s; }
__host__ __device__ constexpr double cexp(double x){ return x < 0.0 ? 1.0/cexp_pos(-x) : cexp_pos(x); }
__host__ __device__ constexpr double ccos(double x){ double x2=x*x,t=1.0,s=1.0; for(int n=1;n<30;n++){ t*=-x2/((2.0*n-1.0)*(2.0*n)); s+=t; } return s; }

struct K7 { float w[7][7]; };

__host__ __device__ constexpr K7 make_log(int r, double sigma){
    double tmp[7][7] = {}; double s = 0.0;
    for(int i=-r;i<=r;i++) for(int j=-r;j<=r;j++){
        double r2 = (double)(i*i + j*j);
        double g  = cexp(-r2/(2.0*sigma*sigma));
        double f  = (1.0 - r2/(2.0*sigma*sigma))*g;
        tmp[i+3][j+3] = -f;
        s += d_abs(f);
    }
    K7 k{};
    for(int i=0;i<7;i++) for(int j=0;j<7;j++) k.w[i][j] = (float)(tmp[i][j]/s);
    return k;
}

__host__ __device__ constexpr K7 make_gabor(double c, double sn){
    double tmp[7][7] = {}; double s = 0.0;
    for(int i=0;i<7;i++) for(int j=0;j<7;j++){
        double x = (double)(j-3), y = (double)(i-3);
        double xt = x*c + y*sn;
        double g = cexp(-(x*x + y*y)/8.0) * ccos(2.0*3.14159265358979323846*0.1*xt);
        tmp[i][j] = g; s += d_abs(g);
    }
    K7 k{};
    for(int i=0;i<7;i++) for(int j=0;j<7;j++) k.w[i][j] = (float)(tmp[i][j]/s);
    return k;
}

__host__ __device__ constexpr K7 make_lpf(){
    K7 k{};
    double b[3] = {0.25, 0.5, 0.25};
    for(int i=0;i<3;i++) for(int j=0;j<3;j++) k.w[i+2][j+2] = (float)(b[i]*b[j]);
    return k;
}

__host__ __device__ constexpr K7 make_hpf3(){
    K7 k{};
    for(int i=2;i<=4;i++) for(int j=2;j<=4;j++) k.w[i][j] = -1.0f;
    k.w[3][3] = 8.0f;
    return k;
}
__host__ __device__ constexpr K7 make_hpf5(){
    K7 k{};
    for(int i=1;i<=5;i++) for(int j=1;j<=5;j++) k.w[i][j] = -1.0f;
    k.w[3][3] = 24.0f;
    return k;
}

__host__ __device__ constexpr K7 make_even(const K7& a){
    K7 k{};
    for(int i=0;i<7;i++) for(int j=0;j<7;j++) k.w[i][j] = (a.w[i][j] + a.w[i][6-j]) * 0.5f;
    return k;
}
__host__ __device__ constexpr K7 make_odd(const K7& a){
    K7 k{};
    for(int i=0;i<7;i++) for(int j=0;j<7;j++) k.w[i][j] = (a.w[i][j] - a.w[i][6-j]) * 0.5f;
    return k;
}

__device__ constexpr double RS2 = 0.70710678118654752440;
__device__ constexpr K7 KL3   = make_log(1, 0.8);
__device__ constexpr K7 KL5   = make_log(2, 1.0);
__device__ constexpr K7 KL7   = make_log(3, 1.4);
__device__ constexpr K7 KG0   = make_gabor( 1.0, 0.0);
__device__ constexpr K7 KG45  = make_gabor( RS2, RS2);
__device__ constexpr K7 KG90  = make_gabor( 0.0, 1.0);
__device__ constexpr K7 KGE   = make_even(KG45);
__device__ constexpr K7 KGO   = make_odd(KG45);
__device__ constexpr K7 KLP   = make_lpf();
__device__ constexpr K7 KH3   = make_hpf3();
__device__ constexpr K7 KH5   = make_hpf5();

// ---------------------------------------------------------------------------
#define IMG_SZ 262144        // 512*512
#define PLANE  12582912      // 48*512*512
#define PITCH  72
#define BROWS  64            // circular buffer rows (&63)

__device__ __forceinline__ float addi(float a, float b){
    float d; asm("fma.rn.f32 %0, %1, 0f3F800000, %2;" : "=f"(d) : "f"(a), "f"(b)); return d;
}
__device__ __forceinline__ float subi(float a, float b){   // a - b
    float d; asm("fma.rn.f32 %0, %1, 0fBF800000, %2;" : "=f"(d) : "f"(b), "f"(a)); return d;
}

__device__ __forceinline__ float tanh01(float z){    // tanh(0.1*z) via MUFU.TANH
    float t;
    asm("tanh.approx.f32 %0, %1;" : "=f"(t) : "f"(z * 0.1f));
    return t;
}

__device__ __forceinline__ void cpasync4(unsigned int daddr, const float* src, unsigned int sz){
    asm volatile("cp.async.ca.shared.global [%0], [%1], 4, %2;"
                 :: "r"(daddr), "l"(src), "r"(sz) : "memory");
}

struct Acc { float l3,l5,l7,h3,h5,lp,g0,g90,gE,gO; };

template<int R>
__device__ __forceinline__ void taps_even(float vs0, float hs1, float hs2, float hs3, Acc& p){
    p.l7  = fmaf(vs0, KL7.w[3+R][3], p.l7);
    p.l7  = fmaf(hs1, KL7.w[3+R][4], p.l7);
    p.l7  = fmaf(hs2, KL7.w[3+R][5], p.l7);
    p.l7  = fmaf(hs3, KL7.w[3+R][6], p.l7);
    p.g0  = fmaf(vs0, KG0.w[3+R][3], p.g0);
    p.g0  = fmaf(hs1, KG0.w[3+R][4], p.g0);
    p.g0  = fmaf(hs2, KG0.w[3+R][5], p.g0);
    p.g0  = fmaf(hs3, KG0.w[3+R][6], p.g0);
    p.g90 = fmaf(vs0, KG90.w[3+R][3], p.g90);
    p.g90 = fmaf(hs1, KG90.w[3+R][4], p.g90);
    p.g90 = fmaf(hs2, KG90.w[3+R][5], p.g90);
    p.g90 = fmaf(hs3, KG90.w[3+R][6], p.g90);
    p.gE  = fmaf(vs0, KGE.w[3+R][3], p.gE);
    p.gE  = fmaf(hs1, KGE.w[3+R][4], p.gE);
    p.gE  = fmaf(hs2, KGE.w[3+R][5], p.gE);
    p.gE  = fmaf(hs3, KGE.w[3+R][6], p.gE);
    if constexpr (R <= 2){
        p.l5 = fmaf(vs0, KL5.w[3+R][3], p.l5);
        p.l5 = fmaf(hs1, KL5.w[3+R][4], p.l5);
        p.l5 = fmaf(hs2, KL5.w[3+R][5], p.l5);
        p.h5 = fmaf(vs0, KH5.w[3+R][3], p.h5);
        p.h5 = fmaf(hs1, KH5.w[3+R][4], p.h5);
        p.h5 = fmaf(hs2, KH5.w[3+R][5], p.h5);
    }
    if constexpr (R <= 1){
        p.l3 = fmaf(vs0, KL3.w[3+R][3], p.l3);
        p.l3 = fmaf(hs1, KL3.w[3+R][4], p.l3);
        p.lp = fmaf(vs0, KLP.w[3+R][3], p.lp);
        p.lp = fmaf(hs1, KLP.w[3+R][4], p.lp);
        p.h3 = fmaf(vs0, KH3.w[3+R][3], p.h3);
        p.h3 = fmaf(hs1, KH3.w[3+R][4], p.h3);
    }
}

template<int R>
__device__ __forceinline__ void taps_odd(float hd1, float hd2, float hd3, Acc& p){
    p.gO = fmaf(hd1, KGO.w[3+R][4], p.gO);
    p.gO = fmaf(hd2, KGO.w[3+R][5], p.gO);
    p.gO = fmaf(hd3, KGO.w[3+R][6], p.gO);
}

__device__ __forceinline__ void load10(const float* p, float v[10]){
    float4 a = *(const float4*)p;
    float4 b = *(const float4*)(p + 4);
    float2 c = *(const float2*)(p + 8);
    v[0]=a.x; v[1]=a.y; v[2]=a.z; v[3]=a.w;
    v[4]=b.x; v[5]=b.y; v[6]=b.z; v[7]=b.w;
    v[8]=c.x; v[9]=c.y;
}

__device__ __forceinline__ void finalize(const Acc& p, float& lf, float& lo, float& ho, float& go){
    lf = p.lp;
    lo = fmaf(tanh01(fmaxf(fmaxf(p.l3, p.l5), p.l7)), 0.5f, 0.5f);
    ho = fmaf(tanh01(fmaxf(p.h3, p.h5)), 0.5f, 0.5f);
    go = tanh01(fmaxf(fmaxf(p.g0, p.g90), p.gE + fabsf(p.gO)));
}

#define STRIP_H 128
#define ITERS   8            // STRIP_H / 16

__global__ __launch_bounds__(256, 4)
void msfilters_kernel(const float* __restrict__ x, float* __restrict__ out, int planes){
    __shared__ __align__(16) float sm[BROWS * PITCH];

    unsigned int smb;
    asm("{ .reg .u64 t; cvta.to.shared.u64 t, %1; cvt.u32.u64 %0, t; }"
        : "=r"(smb) : "l"((const void*)sm));

    const int img    = blockIdx.z;
    const int x0     = blockIdx.x * 64;
    const int ystart = blockIdx.y * STRIP_H;
    const float* src = x + (size_t)img * IMG_SZ;

    // initial fill: logical rows -3..18 -> phys rows 0..21 (runs once)
    for (int idx = threadIdx.x; idx < 22 * 70; idx += 256){
        int r = idx / 70;
        int c = idx - r * 70;
        int gy0 = ystart + r - 3;
        int gx0 = x0 + c - 3;
        float val = 0.0f;
        if ((unsigned)gy0 < 512u && (unsigned)gx0 < 512u) val = __ldg(src + gy0 * 512 + gx0);
        sm[r * PITCH + c] = val;
    }

    const int tx  = threadIdx.x & 15;
    const int ty  = threadIdx.x >> 4;
    const int tx4 = tx * 4;

    // loop-invariant prefetch state: thread owns row ty, cols tx+16j of the halo.
    // srow/gy always point at the FIRST row of window k+1's fill (ystart+19+16k+ty).
    int gy = ystart + 19 + ty;
    const float* srow = src + (size_t)gy * 512 + (x0 - 3 + tx);
    const int gxb = x0 - 3 + tx;
    const bool v0 = ((unsigned)gxb        < 512u);
    const bool v1 = ((unsigned)(gxb + 16) < 512u);
    const bool v2 = ((unsigned)(gxb + 32) < 512u);
    const bool v3 = ((unsigned)(gxb + 48) < 512u);
    const bool v4 = (tx < 6) && ((unsigned)(gxb + 64) < 512u);

    int ybase   = ty;            // (16k + ty) & 63
    int sts_row = 22 + ty;       // window k+1 commit rows: (22 + ty + 16k) & 63

#define ISSUE_PF(STSROW, SPTR, GOK) { \
        unsigned int d0 = smb + (unsigned int)((((STSROW) & 63) * PITCH + tx) * 4); \
        cpasync4(d0,       (SPTR),      (v0 && (GOK)) ? 4u : 0u); \
        cpasync4(d0 + 64,  (SPTR) + 16, (v1 && (GOK)) ? 4u : 0u); \
        cpasync4(d0 + 128, (SPTR) + 32, (v2 && (GOK)) ? 4u : 0u); \
        cpasync4(d0 + 192, (SPTR) + 48, (v3 && (GOK)) ? 4u : 0u); \
        if (tx < 6) \
            cpasync4(d0 + 256, (SPTR) + 64, (v4 && (GOK)) ? 4u : 0u); \
        asm volatile("cp.async.commit_group;" ::: "memory"); }

    float* outp = out + (size_t)img * IMG_SZ + (size_t)(ystart + ty) * 512 + x0 + tx4;

    // prologue: issue window-1 fill (depth-2 pipeline head)
    ISSUE_PF(sts_row, srow, gy < 512)

    __syncthreads();

    #pragma unroll 1
    for (int k = 0; k < ITERS; k++){
        // ---- issue window k+2's fill (2 iterations ahead) ----
        if (k < ITERS - 2){
            ISSUE_PF(sts_row + 16, srow + 16 * 512, (gy + 16) < 512)
        }

        // ---- compute current 16 output rows from circular smem window ----
        const float* rowp[7];
        #pragma unroll
        for (int d = 0; d < 7; d++)
            rowp[d] = &sm[((ybase + d) & 63) * PITCH + tx4];

        Acc acc[4] = {};

        {   // level 0: center row; also emit the 'original' plane right away
            float m[10]; load10(rowp[3], m);
            float4 o4; o4.x = m[3]; o4.y = m[4]; o4.z = m[5]; o4.w = m[6];
            *(float4*)(outp) = o4;
            #pragma unroll
            for (int p = 0; p < 4; p++){
                const int cc = p + 3;
                float hs1 = addi(m[cc-1], m[cc+1]);
                float hs2 = addi(m[cc-2], m[cc+2]);
                float hs3 = addi(m[cc-3], m[cc+3]);
                taps_even<0>(m[cc], hs1, hs2, hs3, acc[p]);
            }
        }

#define LEVEL(R) { \
        float T[10], B[10]; \
        load10(rowp[3-R], T); \
        load10(rowp[3+R], B); \
        float V[10], W[10]; \
        _Pragma("unroll") \
        for (int c = 0; c < 10; c++){ V[c] = addi(T[c], B[c]); W[c] = subi(T[c], B[c]); } \
        _Pragma("unroll") \
        for (int p = 0; p < 4; p++){ \
            const int cc = p + 3; \
            float hs1 = addi(V[cc-1], V[cc+1]); \
            float hs2 = addi(V[cc-2], V[cc+2]); \
            float hs3 = addi(V[cc-3], V[cc+3]); \
            taps_even<R>(V[cc], hs1, hs2, hs3, acc[p]); \
            float hd1 = subi(W[cc-1], W[cc+1]); \
            float hd2 = subi(W[cc-2], W[cc+2]); \
            float hd3 = subi(W[cc-3], W[cc+3]); \
            taps_odd<R>(hd1, hd2, hd3, acc[p]); \
        } }
        LEVEL(1)
        LEVEL(2)
        LEVEL(3)
#undef LEVEL

        float4 lf4, lo4, ho4, go4;
        finalize(acc[0], lf4.x, lo4.x, ho4.x, go4.x);
        finalize(acc[1], lf4.y, lo4.y, ho4.y, go4.y);
        finalize(acc[2], lf4.z, lo4.z, ho4.z, go4.z);
        finalize(acc[3], lf4.w, lo4.w, ho4.w, go4.w);

        *(float4*)(outp + (size_t)PLANE)   = lf4;
        *(float4*)(outp + 2*(size_t)PLANE) = lo4;
        *(float4*)(outp + 3*(size_t)PLANE) = ho4;
        if (planes >= 5)
            *(float4*)(outp + 4*(size_t)PLANE) = go4;

        // need window k+1's fill complete before next iteration reads it.
        // While the k+2 group is still in flight (k < ITERS-2), wait to depth 1;
        // in the drain phase wait for everything.
        if (k < ITERS - 2)
            asm volatile("cp.async.wait_group 1;" ::: "memory");
        else
            asm volatile("cp.async.wait_group 0;" ::: "memory");
        __syncthreads();

        gy      += 16;
        srow    += 16 * 512;
        outp    += 16 * 512;
        ybase   += 16;
        sts_row += 16;
    }
#undef ISSUE_PF
}

extern "C" void kernel_launch(void* const* d_in, const int* in_sizes, int n_in,
                              void* d_out, int out_size){
    const float* x = (const float*)d_in[0];
    float* out = (float*)d_out;
    const int planes = out_size / PLANE;   // 5 when use_gabor
    dim3 grid(8, 512 / STRIP_H, 48);
    dim3 block(256);
    msfilters_kernel<<<grid, block>>>(x, out, planes);
}

// round 13
// speedup vs baseline: 1.0590x; 1.0590x over previous
#include <cuda_runtime.h>

// ---------------------------------------------------------------------------
// Compile-time filter construction (double precision, folded to fp32 imms)
// ---------------------------------------------------------------------------
__host__ __device__ constexpr double d_abs(double x){ return x < 0 ? -x : x; }
__host__ __device__ constexpr double cexp_pos(double x){ double t=1.0,s=1.0; for(int n=1;n<60;n++){ t*=x/n; s+=t; } return s; }
__host__ __device__ constexpr double cexp(double x){ return x < 0.0 ? 1.0/cexp_pos(-x) : cexp_pos(x); }
__host__ __device__ constexpr double ccos(double x){ double x2=x*x,t=1.0,s=1.0; for(int n=1;n<30;n++){ t*=-x2/((2.0*n-1.0)*(2.0*n)); s+=t; } return s; }

struct K7 { float w[7][7]; };

__host__ __device__ constexpr K7 make_log(int r, double sigma){
    double tmp[7][7] = {}; double s = 0.0;
    for(int i=-r;i<=r;i++) for(int j=-r;j<=r;j++){
        double r2 = (double)(i*i + j*j);
        double g  = cexp(-r2/(2.0*sigma*sigma));
        double f  = (1.0 - r2/(2.0*sigma*sigma))*g;
        tmp[i+3][j+3] = -f;
        s += d_abs(f);
    }
    K7 k{};
    for(int i=0;i<7;i++) for(int j=0;j<7;j++) k.w[i][j] = (float)(tmp[i][j]/s);
    return k;
}

__host__ __device__ constexpr K7 make_gabor(double c, double sn){
    double tmp[7][7] = {}; double s = 0.0;
    for(int i=0;i<7;i++) for(int j=0;j<7;j++){
        double x = (double)(j-3), y = (double)(i-3);
        double xt = x*c + y*sn;
        double g = cexp(-(x*x + y*y)/8.0) * ccos(2.0*3.14159265358979323846*0.1*xt);
        tmp[i][j] = g; s += d_abs(g);
    }
    K7 k{};
    for(int i=0;i<7;i++) for(int j=0;j<7;j++) k.w[i][j] = (float)(tmp[i][j]/s);
    return k;
}

__host__ __device__ constexpr K7 make_lpf(){
    K7 k{};
    double b[3] = {0.25, 0.5, 0.25};
    for(int i=0;i<3;i++) for(int j=0;j<3;j++) k.w[i+2][j+2] = (float)(b[i]*b[j]);
    return k;
}

__host__ __device__ constexpr K7 make_hpf3(){
    K7 k{};
    for(int i=2;i<=4;i++) for(int j=2;j<=4;j++) k.w[i][j] = -1.0f;
    k.w[3][3] = 8.0f;
    return k;
}
__host__ __device__ constexpr K7 make_hpf5(){
    K7 k{};
    for(int i=1;i<=5;i++) for(int j=1;j<=5;j++) k.w[i][j] = -1.0f;
    k.w[3][3] = 24.0f;
    return k;
}

__host__ __device__ constexpr K7 make_even(const K7& a){
    K7 k{};
    for(int i=0;i<7;i++) for(int j=0;j<7;j++) k.w[i][j] = (a.w[i][j] + a.w[i][6-j]) * 0.5f;
    return k;
}
__host__ __device__ constexpr K7 make_odd(const K7& a){
    K7 k{};
    for(int i=0;i<7;i++) for(int j=0;j<7;j++) k.w[i][j] = (a.w[i][j] - a.w[i][6-j]) * 0.5f;
    return k;
}

__device__ constexpr double RS2 = 0.70710678118654752440;
__device__ constexpr K7 KL3   = make_log(1, 0.8);
__device__ constexpr K7 KL5   = make_log(2, 1.0);
__device__ constexpr K7 KL7   = make_log(3, 1.4);
__device__ constexpr K7 KG0   = make_gabor( 1.0, 0.0);
__device__ constexpr K7 KG45  = make_gabor( RS2, RS2);
__device__ constexpr K7 KG90  = make_gabor( 0.0, 1.0);
__device__ constexpr K7 KGE   = make_even(KG45);
__device__ constexpr K7 KGO   = make_odd(KG45);
__device__ constexpr K7 KLP   = make_lpf();
__device__ constexpr K7 KH3   = make_hpf3();
__device__ constexpr K7 KH5   = make_hpf5();

// ---------------------------------------------------------------------------
#define IMG_SZ 262144        // 512*512
#define PLANE  12582912      // 48*512*512
#define PITCH  72
#define BROWS  64            // circular buffer rows (&63)

__device__ __forceinline__ float addi(float a, float b){
    float d; asm("fma.rn.f32 %0, %1, 0f3F800000, %2;" : "=f"(d) : "f"(a), "f"(b)); return d;
}
__device__ __forceinline__ float subi(float a, float b){   // a - b
    float d; asm("fma.rn.f32 %0, %1, 0fBF800000, %2;" : "=f"(d) : "f"(b), "f"(a)); return d;
}

__device__ __forceinline__ float tanh01(float z){    // tanh(0.1*z) via MUFU.TANH
    float t;
    asm("tanh.approx.f32 %0, %1;" : "=f"(t) : "f"(z * 0.1f));
    return t;
}

__device__ __forceinline__ void cpasync4(unsigned int daddr, const float* src, unsigned int sz){
    asm volatile("cp.async.ca.shared.global [%0], [%1], 4, %2;"
                 :: "r"(daddr), "l"(src), "r"(sz) : "memory");
}

struct Acc { float l3,l5,l7,h3,h5,lp,g0,g90,gE,gO; };

template<int R>
__device__ __forceinline__ void taps_even(float vs0, float hs1, float hs2, float hs3, Acc& p){
    p.l7  = fmaf(vs0, KL7.w[3+R][3], p.l7);
    p.l7  = fmaf(hs1, KL7.w[3+R][4], p.l7);
    p.l7  = fmaf(hs2, KL7.w[3+R][5], p.l7);
    p.l7  = fmaf(hs3, KL7.w[3+R][6], p.l7);
    p.g0  = fmaf(vs0, KG0.w[3+R][3], p.g0);
    p.g0  = fmaf(hs1, KG0.w[3+R][4], p.g0);
    p.g0  = fmaf(hs2, KG0.w[3+R][5], p.g0);
    p.g0  = fmaf(hs3, KG0.w[3+R][6], p.g0);
    p.g90 = fmaf(vs0, KG90.w[3+R][3], p.g90);
    p.g90 = fmaf(hs1, KG90.w[3+R][4], p.g90);
    p.g90 = fmaf(hs2, KG90.w[3+R][5], p.g90);
    p.g90 = fmaf(hs3, KG90.w[3+R][6], p.g90);
    p.gE  = fmaf(vs0, KGE.w[3+R][3], p.gE);
    p.gE  = fmaf(hs1, KGE.w[3+R][4], p.gE);
    p.gE  = fmaf(hs2, KGE.w[3+R][5], p.gE);
    p.gE  = fmaf(hs3, KGE.w[3+R][6], p.gE);
    if constexpr (R <= 2){
        p.l5 = fmaf(vs0, KL5.w[3+R][3], p.l5);
        p.l5 = fmaf(hs1, KL5.w[3+R][4], p.l5);
        p.l5 = fmaf(hs2, KL5.w[3+R][5], p.l5);
        p.h5 = fmaf(vs0, KH5.w[3+R][3], p.h5);
        p.h5 = fmaf(hs1, KH5.w[3+R][4], p.h5);
        p.h5 = fmaf(hs2, KH5.w[3+R][5], p.h5);
    }
    if constexpr (R <= 1){
        p.l3 = fmaf(vs0, KL3.w[3+R][3], p.l3);
        p.l3 = fmaf(hs1, KL3.w[3+R][4], p.l3);
        p.lp = fmaf(vs0, KLP.w[3+R][3], p.lp);
        p.lp = fmaf(hs1, KLP.w[3+R][4], p.lp);
        p.h3 = fmaf(vs0, KH3.w[3+R][3], p.h3);
        p.h3 = fmaf(hs1, KH3.w[3+R][4], p.h3);
    }
}

template<int R>
__device__ __forceinline__ void taps_odd(float hd1, float hd2, float hd3, Acc& p){
    p.gO = fmaf(hd1, KGO.w[3+R][4], p.gO);
    p.gO = fmaf(hd2, KGO.w[3+R][5], p.gO);
    p.gO = fmaf(hd3, KGO.w[3+R][6], p.gO);
}

__device__ __forceinline__ void load10(const float* p, float v[10]){
    float4 a = *(const float4*)p;
    float4 b = *(const float4*)(p + 4);
    float2 c = *(const float2*)(p + 8);
    v[0]=a.x; v[1]=a.y; v[2]=a.z; v[3]=a.w;
    v[4]=b.x; v[5]=b.y; v[6]=b.z; v[7]=b.w;
    v[8]=c.x; v[9]=c.y;
}

__device__ __forceinline__ void finalize(const Acc& p, float& lf, float& lo, float& ho, float& go){
    lf = p.lp;
    lo = fmaf(tanh01(fmaxf(fmaxf(p.l3, p.l5), p.l7)), 0.5f, 0.5f);
    ho = fmaf(tanh01(fmaxf(p.h3, p.h5)), 0.5f, 0.5f);
    go = tanh01(fmaxf(fmaxf(p.g0, p.g90), p.gE + fabsf(p.gO)));
}

// Uneven y-strips: blockIdx.y 0,1 -> 176 rows (11 iters), blockIdx.y 2 -> 160
// rows (10 iters). Grid = 8*3*48 = 1152 blocks vs 592 concurrent slots:
// wave 2 is 94.6% full (vs 13.6% quantization waste at 1536 blocks).
#define STRIP_H 176

__global__ __launch_bounds__(256, 4)
void msfilters_kernel(const float* __restrict__ x, float* __restrict__ out, int planes){
    __shared__ __align__(16) float sm[BROWS * PITCH];

    unsigned int smb;
    asm("{ .reg .u64 t; cvta.to.shared.u64 t, %1; cvt.u32.u64 %0, t; }"
        : "=r"(smb) : "l"((const void*)sm));

    const int img    = blockIdx.z;
    const int x0     = blockIdx.x * 64;
    const int ystart = blockIdx.y * STRIP_H;
    const int iters  = (blockIdx.y == 2) ? 10 : 11;   // 176+176+160 = 512
    const float* src = x + (size_t)img * IMG_SZ;

    // initial fill: logical rows -3..18 -> phys rows 0..21 (runs once)
    for (int idx = threadIdx.x; idx < 22 * 70; idx += 256){
        int r = idx / 70;
        int c = idx - r * 70;
        int gy0 = ystart + r - 3;
        int gx0 = x0 + c - 3;
        float val = 0.0f;
        if ((unsigned)gy0 < 512u && (unsigned)gx0 < 512u) val = __ldg(src + gy0 * 512 + gx0);
        sm[r * PITCH + c] = val;
    }

    const int tx  = threadIdx.x & 15;
    const int ty  = threadIdx.x >> 4;
    const int tx4 = tx * 4;

    // loop-invariant prefetch state: thread owns row ty, cols tx+16j of the halo
    int gy = ystart + 19 + ty;
    const float* srow = src + (size_t)gy * 512 + (x0 - 3 + tx);
    const int gxb = x0 - 3 + tx;
    const bool v0 = ((unsigned)gxb        < 512u);
    const bool v1 = ((unsigned)(gxb + 16) < 512u);
    const bool v2 = ((unsigned)(gxb + 32) < 512u);
    const bool v3 = ((unsigned)(gxb + 48) < 512u);
    const bool v4 = (tx < 6) && ((unsigned)(gxb + 64) < 512u);

    int ybase   = ty;            // (16k + ty) & 63
    int sts_row = 22 + ty;       // (22 + ty + 16k) & 63

    float* outp = out + (size_t)img * IMG_SZ + (size_t)(ystart + ty) * 512 + x0 + tx4;

    __syncthreads();

    #pragma unroll 1
    for (int k = 0; k < iters; k++){
        // ---- async prefetch of next 16 rows straight into smem ----
        if (k < iters - 1){
            const bool gok = gy < 512;
            unsigned int d0 = smb + (unsigned int)(((sts_row & 63) * PITCH + tx) * 4);
            cpasync4(d0,       srow,      (v0 && gok) ? 4u : 0u);
            cpasync4(d0 + 64,  srow + 16, (v1 && gok) ? 4u : 0u);
            cpasync4(d0 + 128, srow + 32, (v2 && gok) ? 4u : 0u);
            cpasync4(d0 + 192, srow + 48, (v3 && gok) ? 4u : 0u);
            if (tx < 6)
                cpasync4(d0 + 256, srow + 64, (v4 && gok) ? 4u : 0u);
            asm volatile("cp.async.commit_group;" ::: "memory");
        }

        // ---- compute current 16 output rows from circular smem window ----
        const float* rowp[7];
        #pragma unroll
        for (int d = 0; d < 7; d++)
            rowp[d] = &sm[((ybase + d) & 63) * PITCH + tx4];

        Acc acc[4] = {};

        {   // level 0: center row; also emit the 'original' plane right away
            float m[10]; load10(rowp[3], m);
            float4 o4; o4.x = m[3]; o4.y = m[4]; o4.z = m[5]; o4.w = m[6];
            *(float4*)(outp) = o4;
            #pragma unroll
            for (int p = 0; p < 4; p++){
                const int cc = p + 3;
                float hs1 = addi(m[cc-1], m[cc+1]);
                float hs2 = addi(m[cc-2], m[cc+2]);
                float hs3 = addi(m[cc-3], m[cc+3]);
                taps_even<0>(m[cc], hs1, hs2, hs3, acc[p]);
            }
        }

#define LEVEL(R) { \
        float T[10], B[10]; \
        load10(rowp[3-R], T); \
        load10(rowp[3+R], B); \
        float V[10], W[10]; \
        _Pragma("unroll") \
        for (int c = 0; c < 10; c++){ V[c] = addi(T[c], B[c]); W[c] = subi(T[c], B[c]); } \
        _Pragma("unroll") \
        for (int p = 0; p < 4; p++){ \
            const int cc = p + 3; \
            float hs1 = addi(V[cc-1], V[cc+1]); \
            float hs2 = addi(V[cc-2], V[cc+2]); \
            float hs3 = addi(V[cc-3], V[cc+3]); \
            taps_even<R>(V[cc], hs1, hs2, hs3, acc[p]); \
            float hd1 = subi(W[cc-1], W[cc+1]); \
            float hd2 = subi(W[cc-2], W[cc+2]); \
            float hd3 = subi(W[cc-3], W[cc+3]); \
            taps_odd<R>(hd1, hd2, hd3, acc[p]); \
        } }
        LEVEL(1)
        LEVEL(2)
        LEVEL(3)
#undef LEVEL

        float4 lf4, lo4, ho4, go4;
        finalize(acc[0], lf4.x, lo4.x, ho4.x, go4.x);
        finalize(acc[1], lf4.y, lo4.y, ho4.y, go4.y);
        finalize(acc[2], lf4.z, lo4.z, ho4.z, go4.z);
        finalize(acc[3], lf4.w, lo4.w, ho4.w, go4.w);

        *(float4*)(outp + (size_t)PLANE)   = lf4;
        *(float4*)(outp + 2*(size_t)PLANE) = lo4;
        *(float4*)(outp + 3*(size_t)PLANE) = ho4;
        if (planes >= 5)
            *(float4*)(outp + 4*(size_t)PLANE) = go4;

        // prefetch rows are disjoint (mod 64) from this iteration's read
        // window, so a single barrier per iteration suffices.
        asm volatile("cp.async.wait_group 0;" ::: "memory");
        __syncthreads();

        gy      += 16;
        srow    += 16 * 512;
        outp    += 16 * 512;
        ybase   += 16;
        sts_row += 16;
    }
}

extern "C" void kernel_launch(void* const* d_in, const int* in_sizes, int n_in,
                              void* d_out, int out_size){
    const float* x = (const float*)d_in[0];
    float* out = (float*)d_out;
    const int planes = out_size / PLANE;   // 5 when use_gabor
    dim3 grid(8, 3, 48);
    dim3 block(256);
    msfilters_kernel<<<grid, block>>>(x, out, planes);
}

// round 14
// speedup vs baseline: 1.0890x; 1.0283x over previous
#include <cuda_runtime.h>

// ---------------------------------------------------------------------------
// Compile-time filter construction (double precision, folded to fp32 imms)
// ---------------------------------------------------------------------------
__host__ __device__ constexpr double d_abs(double x){ return x < 0 ? -x : x; }
__host__ __device__ constexpr double cexp_pos(double x){ double t=1.0,s=1.0; for(int n=1;n<60;n++){ t*=x/n; s+=t; } return s; }
__host__ __device__ constexpr double cexp(double x){ return x < 0.0 ? 1.0/cexp_pos(-x) : cexp_pos(x); }
__host__ __device__ constexpr double ccos(double x){ double x2=x*x,t=1.0,s=1.0; for(int n=1;n<30;n++){ t*=-x2/((2.0*n-1.0)*(2.0*n)); s+=t; } return s; }

struct K7 { float w[7][7]; };

__host__ __device__ constexpr K7 make_log(int r, double sigma){
    double tmp[7][7] = {}; double s = 0.0;
    for(int i=-r;i<=r;i++) for(int j=-r;j<=r;j++){
        double r2 = (double)(i*i + j*j);
        double g  = cexp(-r2/(2.0*sigma*sigma));
        double f  = (1.0 - r2/(2.0*sigma*sigma))*g;
        tmp[i+3][j+3] = -f;
        s += d_abs(f);
    }
    K7 k{};
    for(int i=0;i<7;i++) for(int j=0;j<7;j++) k.w[i][j] = (float)(tmp[i][j]/s);
    return k;
}

__host__ __device__ constexpr K7 make_gabor(double c, double sn){
    double tmp[7][7] = {}; double s = 0.0;
    for(int i=0;i<7;i++) for(int j=0;j<7;j++){
        double x = (double)(j-3), y = (double)(i-3);
        double xt = x*c + y*sn;
        double g = cexp(-(x*x + y*y)/8.0) * ccos(2.0*3.14159265358979323846*0.1*xt);
        tmp[i][j] = g; s += d_abs(g);
    }
    K7 k{};
    for(int i=0;i<7;i++) for(int j=0;j<7;j++) k.w[i][j] = (float)(tmp[i][j]/s);
    return k;
}

__host__ __device__ constexpr K7 make_lpf(){
    K7 k{};
    double b[3] = {0.25, 0.5, 0.25};
    for(int i=0;i<3;i++) for(int j=0;j<3;j++) k.w[i+2][j+2] = (float)(b[i]*b[j]);
    return k;
}

__host__ __device__ constexpr K7 make_hpf3(){
    K7 k{};
    for(int i=2;i<=4;i++) for(int j=2;j<=4;j++) k.w[i][j] = -1.0f;
    k.w[3][3] = 8.0f;
    return k;
}
__host__ __device__ constexpr K7 make_hpf5(){
    K7 k{};
    for(int i=1;i<=5;i++) for(int j=1;j<=5;j++) k.w[i][j] = -1.0f;
    k.w[3][3] = 24.0f;
    return k;
}

__host__ __device__ constexpr K7 make_even(const K7& a){
    K7 k{};
    for(int i=0;i<7;i++) for(int j=0;j<7;j++) k.w[i][j] = (a.w[i][j] + a.w[i][6-j]) * 0.5f;
    return k;
}
__host__ __device__ constexpr K7 make_odd(const K7& a){
    K7 k{};
    for(int i=0;i<7;i++) for(int j=0;j<7;j++) k.w[i][j] = (a.w[i][j] - a.w[i][6-j]) * 0.5f;
    return k;
}

__device__ constexpr double RS2 = 0.70710678118654752440;
__device__ constexpr K7 KL3   = make_log(1, 0.8);
__device__ constexpr K7 KL5   = make_log(2, 1.0);
__device__ constexpr K7 KL7   = make_log(3, 1.4);
__device__ constexpr K7 KG0   = make_gabor( 1.0, 0.0);
__device__ constexpr K7 KG45  = make_gabor( RS2, RS2);
__device__ constexpr K7 KG90  = make_gabor( 0.0, 1.0);
__device__ constexpr K7 KGE   = make_even(KG45);
__device__ constexpr K7 KGO   = make_odd(KG45);
__device__ constexpr K7 KLP   = make_lpf();
__device__ constexpr K7 KH3   = make_hpf3();
__device__ constexpr K7 KH5   = make_hpf5();

// ---------------------------------------------------------------------------
#define IMG_SZ 262144        // 512*512
#define PLANE  12582912      // 48*512*512
#define PITCH  72
#define BROWS  64            // circular buffer rows (&63)

__device__ __forceinline__ float addi(float a, float b){
    float d; asm("fma.rn.f32 %0, %1, 0f3F800000, %2;" : "=f"(d) : "f"(a), "f"(b)); return d;
}
__device__ __forceinline__ float subi(float a, float b){   // a - b
    float d; asm("fma.rn.f32 %0, %1, 0fBF800000, %2;" : "=f"(d) : "f"(b), "f"(a)); return d;
}

__device__ __forceinline__ float tanh01(float z){    // tanh(0.1*z) via MUFU.TANH
    float t;
    asm("tanh.approx.f32 %0, %1;" : "=f"(t) : "f"(z * 0.1f));
    return t;
}

__device__ __forceinline__ void cpasync4(unsigned int daddr, const float* src, unsigned int sz){
    asm volatile("cp.async.ca.shared.global [%0], [%1], 4, %2;"
                 :: "r"(daddr), "l"(src), "r"(sz) : "memory");
}

struct Acc { float l3,l5,l7,h3,h5,lp,g0,g90,gE,gO; };

// Even-symmetric taps for fold-level R. Processed in DESCENDING R order so
// the narrow-filter accumulators (l3/lp/h3 at R<=1, l5/h5 at R<=2) only come
// alive late, minimizing peak register pressure during the wide levels.
template<int R>
__device__ __forceinline__ void taps_even(float vs0, float hs1, float hs2, float hs3, Acc& p){
    p.l7  = fmaf(vs0, KL7.w[3+R][3], p.l7);
    p.l7  = fmaf(hs1, KL7.w[3+R][4], p.l7);
    p.l7  = fmaf(hs2, KL7.w[3+R][5], p.l7);
    p.l7  = fmaf(hs3, KL7.w[3+R][6], p.l7);
    p.g0  = fmaf(vs0, KG0.w[3+R][3], p.g0);
    p.g0  = fmaf(hs1, KG0.w[3+R][4], p.g0);
    p.g0  = fmaf(hs2, KG0.w[3+R][5], p.g0);
    p.g0  = fmaf(hs3, KG0.w[3+R][6], p.g0);
    p.g90 = fmaf(vs0, KG90.w[3+R][3], p.g90);
    p.g90 = fmaf(hs1, KG90.w[3+R][4], p.g90);
    p.g90 = fmaf(hs2, KG90.w[3+R][5], p.g90);
    p.g90 = fmaf(hs3, KG90.w[3+R][6], p.g90);
    p.gE  = fmaf(vs0, KGE.w[3+R][3], p.gE);
    p.gE  = fmaf(hs1, KGE.w[3+R][4], p.gE);
    p.gE  = fmaf(hs2, KGE.w[3+R][5], p.gE);
    p.gE  = fmaf(hs3, KGE.w[3+R][6], p.gE);
    if constexpr (R <= 2){
        p.l5 = fmaf(vs0, KL5.w[3+R][3], p.l5);
        p.l5 = fmaf(hs1, KL5.w[3+R][4], p.l5);
        p.l5 = fmaf(hs2, KL5.w[3+R][5], p.l5);
        p.h5 = fmaf(vs0, KH5.w[3+R][3], p.h5);
        p.h5 = fmaf(hs1, KH5.w[3+R][4], p.h5);
        p.h5 = fmaf(hs2, KH5.w[3+R][5], p.h5);
    }
    if constexpr (R <= 1){
        p.l3 = fmaf(vs0, KL3.w[3+R][3], p.l3);
        p.l3 = fmaf(hs1, KL3.w[3+R][4], p.l3);
        p.lp = fmaf(vs0, KLP.w[3+R][3], p.lp);
        p.lp = fmaf(hs1, KLP.w[3+R][4], p.lp);
        p.h3 = fmaf(vs0, KH3.w[3+R][3], p.h3);
        p.h3 = fmaf(hs1, KH3.w[3+R][4], p.h3);
    }
}

template<int R>
__device__ __forceinline__ void taps_odd(float hd1, float hd2, float hd3, Acc& p){
    p.gO = fmaf(hd1, KGO.w[3+R][4], p.gO);
    p.gO = fmaf(hd2, KGO.w[3+R][5], p.gO);
    p.gO = fmaf(hd3, KGO.w[3+R][6], p.gO);
}

__device__ __forceinline__ void load10(const float* p, float v[10]){
    float4 a = *(const float4*)p;
    float4 b = *(const float4*)(p + 4);
    float2 c = *(const float2*)(p + 8);
    v[0]=a.x; v[1]=a.y; v[2]=a.z; v[3]=a.w;
    v[4]=b.x; v[5]=b.y; v[6]=b.z; v[7]=b.w;
    v[8]=c.x; v[9]=c.y;
}

__device__ __forceinline__ void finalize(const Acc& p, float& lf, float& lo, float& ho, float& go){
    lf = p.lp;
    lo = fmaf(tanh01(fmaxf(fmaxf(p.l3, p.l5), p.l7)), 0.5f, 0.5f);
    ho = fmaf(tanh01(fmaxf(p.h3, p.h5)), 0.5f, 0.5f);
    go = tanh01(fmaxf(fmaxf(p.g0, p.g90), p.gE + fabsf(p.gO)));
}

// Uneven y-strips: blockIdx.y 0,1 -> 176 rows (11 iters), blockIdx.y 2 -> 160
// rows (10 iters). Grid = 8*3*48 = 1152 blocks.
#define STRIP_H 176

__global__ __launch_bounds__(256, 4)
void msfilters_kernel(const float* __restrict__ x, float* __restrict__ out, int planes){
    __shared__ __align__(16) float sm[BROWS * PITCH];

    unsigned int smb;
    asm("{ .reg .u64 t; cvta.to.shared.u64 t, %1; cvt.u32.u64 %0, t; }"
        : "=r"(smb) : "l"((const void*)sm));

    const int img    = blockIdx.z;
    const int x0     = blockIdx.x * 64;
    const int ystart = blockIdx.y * STRIP_H;
    const int iters  = (blockIdx.y == 2) ? 10 : 11;   // 176+176+160 = 512
    const float* src = x + (size_t)img * IMG_SZ;

    // initial fill: logical rows -3..18 -> phys rows 0..21 (runs once)
    for (int idx = threadIdx.x; idx < 22 * 70; idx += 256){
        int r = idx / 70;
        int c = idx - r * 70;
        int gy0 = ystart + r - 3;
        int gx0 = x0 + c - 3;
        float val = 0.0f;
        if ((unsigned)gy0 < 512u && (unsigned)gx0 < 512u) val = __ldg(src + gy0 * 512 + gx0);
        sm[r * PITCH + c] = val;
    }

    const int tx  = threadIdx.x & 15;
    const int ty  = threadIdx.x >> 4;
    const int tx4 = tx * 4;

    // loop-invariant prefetch state: thread owns row ty, cols tx+16j of the halo
    int gy = ystart + 19 + ty;
    const float* srow = src + (size_t)gy * 512 + (x0 - 3 + tx);
    const int gxb = x0 - 3 + tx;
    const bool v0 = ((unsigned)gxb        < 512u);
    const bool v1 = ((unsigned)(gxb + 16) < 512u);
    const bool v2 = ((unsigned)(gxb + 32) < 512u);
    const bool v3 = ((unsigned)(gxb + 48) < 512u);
    const bool v4 = (tx < 6) && ((unsigned)(gxb + 64) < 512u);

    int ybase   = ty;            // (16k + ty) & 63
    int sts_row = 22 + ty;       // (22 + ty + 16k) & 63

    float* outp = out + (size_t)img * IMG_SZ + (size_t)(ystart + ty) * 512 + x0 + tx4;

    __syncthreads();

    #pragma unroll 1
    for (int k = 0; k < iters; k++){
        // ---- async prefetch of next 16 rows straight into smem ----
        if (k < iters - 1){
            const bool gok = gy < 512;
            unsigned int d0 = smb + (unsigned int)(((sts_row & 63) * PITCH + tx) * 4);
            cpasync4(d0,       srow,      (v0 && gok) ? 4u : 0u);
            cpasync4(d0 + 64,  srow + 16, (v1 && gok) ? 4u : 0u);
            cpasync4(d0 + 128, srow + 32, (v2 && gok) ? 4u : 0u);
            cpasync4(d0 + 192, srow + 48, (v3 && gok) ? 4u : 0u);
            if (tx < 6)
                cpasync4(d0 + 256, srow + 64, (v4 && gok) ? 4u : 0u);
            asm volatile("cp.async.commit_group;" ::: "memory");
        }

        // ---- compute current 16 output rows from circular smem window ----
        const float* rowp[7];
        #pragma unroll
        for (int d = 0; d < 7; d++)
            rowp[d] = &sm[((ybase + d) & 63) * PITCH + tx4];

        Acc acc[4] = {};

#define LEVEL(R) { \
        float T[10], B[10]; \
        load10(rowp[3-R], T); \
        load10(rowp[3+R], B); \
        float V[10], W[10]; \
        _Pragma("unroll") \
        for (int c = 0; c < 10; c++){ V[c] = addi(T[c], B[c]); W[c] = subi(T[c], B[c]); } \
        _Pragma("unroll") \
        for (int p = 0; p < 4; p++){ \
            const int cc = p + 3; \
            float hs1 = addi(V[cc-1], V[cc+1]); \
            float hs2 = addi(V[cc-2], V[cc+2]); \
            float hs3 = addi(V[cc-3], V[cc+3]); \
            taps_even<R>(V[cc], hs1, hs2, hs3, acc[p]); \
            float hd1 = subi(W[cc-1], W[cc+1]); \
            float hd2 = subi(W[cc-2], W[cc+2]); \
            float hd3 = subi(W[cc-3], W[cc+3]); \
            taps_odd<R>(hd1, hd2, hd3, acc[p]); \
        } }
        // Descending level order: wide filters first (5 accs live), narrow
        // accumulators materialize late -> minimal peak pressure, no spills.
        LEVEL(3)
        LEVEL(2)
        LEVEL(1)
#undef LEVEL

        {   // level 0 (center row) last; also emit the 'original' plane
            float m[10]; load10(rowp[3], m);
            float4 o4; o4.x = m[3]; o4.y = m[4]; o4.z = m[5]; o4.w = m[6];
            *(float4*)(outp) = o4;
            #pragma unroll
            for (int p = 0; p < 4; p++){
                const int cc = p + 3;
                float hs1 = addi(m[cc-1], m[cc+1]);
                float hs2 = addi(m[cc-2], m[cc+2]);
                float hs3 = addi(m[cc-3], m[cc+3]);
                taps_even<0>(m[cc], hs1, hs2, hs3, acc[p]);
            }
        }

        float4 lf4, lo4, ho4, go4;
        finalize(acc[0], lf4.x, lo4.x, ho4.x, go4.x);
        finalize(acc[1], lf4.y, lo4.y, ho4.y, go4.y);
        finalize(acc[2], lf4.z, lo4.z, ho4.z, go4.z);
        finalize(acc[3], lf4.w, lo4.w, ho4.w, go4.w);

        *(float4*)(outp + (size_t)PLANE)   = lf4;
        *(float4*)(outp + 2*(size_t)PLANE) = lo4;
        *(float4*)(outp + 3*(size_t)PLANE) = ho4;
        if (planes >= 5)
            *(float4*)(outp + 4*(size_t)PLANE) = go4;

        // prefetch rows are disjoint (mod 64) from this iteration's read
        // window, so a single barrier per iteration suffices.
        asm volatile("cp.async.wait_group 0;" ::: "memory");
        __syncthreads();

        gy      += 16;
        srow    += 16 * 512;
        outp    += 16 * 512;
        ybase   += 16;
        sts_row += 16;
    }
}

extern "C" void kernel_launch(void* const* d_in, const int* in_sizes, int n_in,
                              void* d_out, int out_size){
    const float* x = (const float*)d_in[0];
    float* out = (float*)d_out;
    const int planes = out_size / PLANE;   // 5 when use_gabor
    dim3 grid(8, 3, 48);
    dim3 block(256);
    msfilters_kernel<<<grid, block>>>(x, out, planes);
}